// round 8
// baseline (speedup 1.0000x reference)
#include <cuda_runtime.h>
#include <math.h>

#define BATCH   16384
#define TSTEPS  300
#define NBASIS  32
#define HID     64
#define DTC     (1.0f/300.0f)
#define BPB     64               // batches per block
#define THREADS 256              // 128 channels x 2 time-halves
#define NBLOCKS (BATCH/BPB)      // 256

#define OFF_SIG ((size_t)BATCH*2*TSTEPS)
#define OFF_VAL (OFF_SIG + (size_t)BATCH*2)

// ---- shared memory layout (floats) ----
// Persistent region first; HT/W2S setup block at the end is ALIASED by the
// rollout transpose buffers (TR) after a __syncthreads() barrier.
#define SH_XR    0                    // 608 : (x_k, rdt_k) float2 table
#define SH_WD    (SH_XR + 608)        // 192 : w2 rows 0,1,65
#define SH_SW    (SH_WD + 192)        // 128
#define SH_VW    (SH_SW + 128)        // 128
#define SH_Q     (SH_VW + 128)        // 640 : poly-coeff map [d][m][k]
#define SH_P     (SH_Q + 640)         // 160 : P[m][j] basis->poly
#define SH_B     (SH_P + 160)         // 24
#define SH_F1W   (SH_B + 24)          // 192
#define SH_F1B   (SH_F1W + 192)       // 64
#define SH_V     (SH_F1B + 64)        // 128 : value head per channel
#define SH_HT    (SH_V + 128)         // 4096: hidden transposed [64][64] (dead after GEMV)
#define SH_W2S   (SH_HT + 4096)       // 4096: w2 rows 2..65 stage (dead after Q build)
#define SH_TR    SH_HT                // 7936: 8 warps x [32][31], aliases HT+W2S
#define SH_TOTAL (SH_HT + 8192)       // 10456 floats = 41824 bytes (< 48KB default cap)

// One Euler step. Every op is an explicitly-rounded IEEE op, so half-0 and
// half-1 threads produce bit-identical (y,z) trajectories.
__device__ __forceinline__ float dmp_step(float2 xv,
                                          float c0, float c1, float c2, float c3, float c4,
                                          float Pg, float nP1, float K1,
                                          float& y, float& z)
{
    float h = __fmaf_rn(__fmaf_rn(__fmaf_rn(__fmaf_rn(c4, xv.x, c3),
                                            xv.x, c2), xv.x, c1), xv.x, c0);
    float u = __fmaf_rn(h, xv.y, Pg);
    u = __fmaf_rn(nP1, y, u);                  // uses OLD y
    float inc  = __fmul_rn(z, DTC);
    float ynew = __fadd_rn(y, inc);
    float dy   = ynew - y;                     // Sterbenz-exact a[t]
    z = __fmaf_rn(K1, z, u);                   // uses OLD z
    y = ynew;
    return dy;
}

extern "C" __global__ void __launch_bounds__(THREADS)
ndp_kernel(const float* __restrict__ state,
           const float* __restrict__ fc1w, const float* __restrict__ fc1b,
           const float* __restrict__ w2,   const float* __restrict__ b2,
           const float* __restrict__ sw,   const float* __restrict__ sb,
           const float* __restrict__ vw,   const float* __restrict__ vb,
           const float* __restrict__ dc,   const float* __restrict__ ds2,
           float* __restrict__ out)
{
    extern __shared__ float sm[];
    const int tid  = threadIdx.x;
    const int bk   = blockIdx.x;
    const int lane = tid & 31;
    const int warp = tid >> 5;
    const int half = tid >> 7;            // 0: steps 0-149, 1: steps 150-299
    const int cid  = tid & 127;           // channel within block

    // ---- phase 1: stage weights; P in warp 0 ----
    for (int i = tid; i < 128; i += THREADS) sm[SH_WD + i] = w2[i];                // rows 0,1
    for (int i = tid; i < 64;  i += THREADS) sm[SH_WD + 128 + i] = w2[65*HID + i]; // row 65
    for (int i = tid; i < 4096; i += THREADS) sm[SH_W2S + i] = w2[2*HID + i];      // rows 2..65
    for (int i = tid; i < 128; i += THREADS) { sm[SH_SW + i] = sw[i]; sm[SH_VW + i] = vw[i]; }
    for (int i = tid; i < 192; i += THREADS) sm[SH_F1W + i] = fc1w[i];
    for (int i = tid; i < 64;  i += THREADS) sm[SH_F1B + i] = fc1b[i];
    if (tid == 0) {
        sm[SH_B + 0] = b2[0]; sm[SH_B + 1] = b2[1]; sm[SH_B + 2] = b2[65];
        sm[SH_B + 3] = sb[0]; sm[SH_B + 4] = sb[1];
        sm[SH_B + 5] = vb[0]; sm[SH_B + 6] = vb[1];
    }
    // P[m][j]: 2nd-order Taylor of exp RBF -> quartic basis (truncation ~2e-10)
    if (warp == 0) {
        float c  = dc[lane], s2 = ds2[lane];
        float a  = 0.5f / s2, a2 = a*a, c2 = c*c;
        float p0 = 1.0f - a*c2 + 0.5f*a2*c2*c2;
        float p1 = 2.0f*a*c - 2.0f*a2*c2*c;
        float p2 = -a + 3.0f*a2*c2;
        float p3 = -2.0f*a2*c;
        float p4 = 0.5f*a2;
        sm[SH_P + 0*32 + lane] = p0;
        sm[SH_P + 1*32 + lane] = p1;
        sm[SH_P + 2*32 + lane] = p2;
        sm[SH_P + 3*32 + lane] = p3;
        sm[SH_P + 4*32 + lane] = p4;
        #pragma unroll
        for (int o = 16; o; o >>= 1) {
            p0 += __shfl_xor_sync(0xffffffffu, p0, o);
            p1 += __shfl_xor_sync(0xffffffffu, p1, o);
            p2 += __shfl_xor_sync(0xffffffffu, p2, o);
            p3 += __shfl_xor_sync(0xffffffffu, p3, o);
            p4 += __shfl_xor_sync(0xffffffffu, p4, o);
        }
        if (lane == 0) {
            sm[SH_B + 7]  = p0; sm[SH_B + 8]  = p1; sm[SH_B + 9] = p2;
            sm[SH_B + 10] = p3; sm[SH_B + 11] = p4;
        }
    }
    __syncthreads();

    // ---- phase 2: fc1 hidden (transposed), XR table, Q, C ----
    {
        int bb = tid & 63;
        int gb = bk*BPB + bb;
        float s0 = state[gb*3+0], s1 = state[gb*3+1], s2v = state[gb*3+2];
        for (int hh = (tid >> 6); hh < HID; hh += 4) {
            float v = sm[SH_F1W + hh*3+0]*s0 + sm[SH_F1W + hh*3+1]*s1
                    + sm[SH_F1W + hh*3+2]*s2v + sm[SH_F1B + hh];
            sm[SH_HT + hh*64 + bb] = tanhf(v) * 0.1f;
        }
    }
    {
        float S0 = sm[SH_B+7], S1 = sm[SH_B+8], S2 = sm[SH_B+9],
              S3 = sm[SH_B+10], S4 = sm[SH_B+11];
        float l2 = log2f(1.0f - DTC);
        for (int k = tid; k < TSTEPS; k += THREADS) {
            float x = exp2f((float)(k + 1) * l2);
            float S = __fmaf_rn(__fmaf_rn(__fmaf_rn(__fmaf_rn(S4,x,S3),x,S2),x,S1),x,S0);
            sm[SH_XR + 2*k]     = x;
            sm[SH_XR + 2*k + 1] = __fdividef(x * DTC, S);
        }
    }
    // Q[d][m][k] = sum_j w2s[(d*32+j)*64 + k] * P[m][j]   (all LDS)
    for (int o = tid; o < 2*5*HID; o += THREADS) {
        int k = o & 63;
        int m = (o >> 6) % 5;
        int d = o / (5*HID);
        const float* wr = sm + SH_W2S + (d*32)*HID + k;
        float acc = 0.0f;
        #pragma unroll 8
        for (int j = 0; j < NBASIS; j++)
            acc += wr[j*HID] * sm[SH_P + m*32 + j];
        sm[SH_Q + o] = acc;
    }
    if (tid < 10) {
        int d = tid / 5, m = tid % 5;
        float acc = 0.0f;
        for (int j = 0; j < NBASIS; j++)
            acc += b2[2 + d*32 + j] * sm[SH_P + m*32 + j];
        sm[SH_B + 12 + tid] = acc;
    }
    __syncthreads();   // W2S reads done

    // ---- per-channel GEMV (duplicated across both halves) ----
    const int b  = cid >> 1;
    const int d  = cid & 1;
    const int gb = bk*BPB + b;

    float goal = sm[SH_B + d];
    float azv  = sm[SH_B + 2];
    float sgp  = sm[SH_B + 3 + d];
    float vlp  = sm[SH_B + 5 + d];
    float c0 = sm[SH_B + 12 + d*5 + 0], c1 = sm[SH_B + 12 + d*5 + 1];
    float c2 = sm[SH_B + 12 + d*5 + 2], c3 = sm[SH_B + 12 + d*5 + 3];
    float c4 = sm[SH_B + 12 + d*5 + 4];

    #pragma unroll
    for (int k = 0; k < HID; k += 4) {
        float h0 = sm[SH_HT + (k+0)*64 + b];
        float h1 = sm[SH_HT + (k+1)*64 + b];
        float h2 = sm[SH_HT + (k+2)*64 + b];
        float h3 = sm[SH_HT + (k+3)*64 + b];
        float4 wg = *(const float4*)(sm + SH_WD + d*64 + k);
        goal += h0*wg.x + h1*wg.y + h2*wg.z + h3*wg.w;
        float4 wa = *(const float4*)(sm + SH_WD + 128 + k);
        azv  += h0*wa.x + h1*wa.y + h2*wa.z + h3*wa.w;
        float4 ws = *(const float4*)(sm + SH_SW + d*64 + k);
        sgp  += h0*ws.x + h1*ws.y + h2*ws.z + h3*ws.w;
        float4 wvv = *(const float4*)(sm + SH_VW + d*64 + k);
        vlp  += h0*wvv.x + h1*wvv.y + h2*wvv.z + h3*wvv.w;
        float4 q;
        q = *(const float4*)(sm + SH_Q + (d*5+0)*64 + k);
        c0 += h0*q.x + h1*q.y + h2*q.z + h3*q.w;
        q = *(const float4*)(sm + SH_Q + (d*5+1)*64 + k);
        c1 += h0*q.x + h1*q.y + h2*q.z + h3*q.w;
        q = *(const float4*)(sm + SH_Q + (d*5+2)*64 + k);
        c2 += h0*q.x + h1*q.y + h2*q.z + h3*q.w;
        q = *(const float4*)(sm + SH_Q + (d*5+3)*64 + k);
        c3 += h0*q.x + h1*q.y + h2*q.z + h3*q.w;
        q = *(const float4*)(sm + SH_Q + (d*5+4)*64 + k);
        c4 += h0*q.x + h1*q.y + h2*q.z + h3*q.w;
    }
    __syncthreads();   // HT reads done -> TR may now alias HT/W2S block

    azv = fminf(fmaxf(azv, 0.5f), 30.0f);
    if (half == 0) {
        out[OFF_SIG + (size_t)bk*128 + cid] = 1.0f / (1.0f + expf(-sgp)) + 0.001f;
        sm[SH_V + cid] = vlp;
    }

    const float y0 = state[gb*3 + d];
    const float G  = goal - y0;
    c0 *= G; c1 *= G; c2 *= G; c3 *= G; c4 *= G;

    const float bz  = azv * 0.25f;
    const float P1  = DTC * azv * bz;
    const float Pg  = P1 * goal;
    const float nP1 = -P1;
    const float K1  = 1.0f - DTC * azv;

    // ---- DMP rollout: half-1 fast-forwards 150 steps (bit-exact, no stores) ----
    float y = y0, z = 0.01f;
    const float2* xr = (const float2*)(sm + SH_XR);

    if (half) {
        #pragma unroll 6
        for (int k = 0; k < 150; k++)
            (void)dmp_step(xr[k], c0, c1, c2, c3, c4, Pg, nP1, K1, y, z);
    }

    float* trb   = sm + SH_TR + warp*(32*31);
    float* out_a = out + (size_t)bk*128*TSTEPS;
    const int wch = (warp & 3) * 32;      // channel base of this warp's trb rows

    for (int ch = half*5; ch < half*5 + 5; ch++) {
        #pragma unroll 6
        for (int s = 0; s < 30; s++) {
            float dy = dmp_step(xr[ch*30 + s], c0, c1, c2, c3, c4, Pg, nP1, K1, y, z);
            trb[lane*31 + s] = dy;
        }
        __syncwarp();
        int t0 = ch*30;
        #pragma unroll
        for (int i = 0; i < 32; i++) {
            if (lane < 30)
                out_a[(size_t)(wch + i)*TSTEPS + t0 + lane] = trb[i*31 + lane];
        }
        __syncwarp();
    }

    // ---- value broadcast fill: 8 warps x 16 channels, coalesced float4 ----
    __syncthreads();
    float* out_v = out + OFF_VAL + (size_t)bk*128*TSTEPS;
    #pragma unroll 4
    for (int c = 0; c < 16; c++) {
        int chn = warp*16 + c;
        float v = sm[SH_V + chn];
        float4 vv = make_float4(v, v, v, v);
        float* base = out_v + (size_t)chn*TSTEPS;
        *(float4*)(base + 4*lane)        = vv;
        *(float4*)(base + 4*(32 + lane)) = vv;
        if (lane < 11) *(float4*)(base + 4*(64 + lane)) = vv;   // 75 = 32+32+11
    }
}

extern "C" void kernel_launch(void* const* d_in, const int* in_sizes, int n_in,
                              void* d_out, int out_size)
{
    (void)in_sizes; (void)n_in; (void)out_size;
    // 41824 B < 48KB default cap; attribute kept as harmless belt-and-suspenders.
    cudaFuncSetAttribute(ndp_kernel, cudaFuncAttributeMaxDynamicSharedMemorySize,
                         SH_TOTAL * (int)sizeof(float));
    ndp_kernel<<<NBLOCKS, THREADS, SH_TOTAL * sizeof(float)>>>(
        (const float*)d_in[0],  (const float*)d_in[1], (const float*)d_in[2],
        (const float*)d_in[3],  (const float*)d_in[4], (const float*)d_in[5],
        (const float*)d_in[6],  (const float*)d_in[7], (const float*)d_in[8],
        (const float*)d_in[9],  (const float*)d_in[10], (float*)d_out);
}

// round 9
// speedup vs baseline: 1.1699x; 1.1699x over previous
#include <cuda_runtime.h>
#include <math.h>

#define BATCH   16384
#define TSTEPS  300
#define NBASIS  32
#define HID     64
#define DTC     (1.0f/300.0f)
#define BPB     64               // batches per block
#define THREADS 128              // 1 thread = 1 channel
#define NBLOCKS (BATCH/BPB)      // 256

#define OFF_SIG ((size_t)BATCH*2*TSTEPS)
#define OFF_VAL (OFF_SIG + (size_t)BATCH*2)

// ---- shared memory layout (floats) ----
#define SH_XR    0                    // 608 : (x_k, rdt_k) float2 table
#define SH_WD    (SH_XR + 608)        // 192 : w2 rows 0,1,65
#define SH_SW    (SH_WD + 192)        // 128
#define SH_VW    (SH_SW + 128)        // 128
#define SH_Q     (SH_VW + 128)        // 640 : poly-coeff map [d][m][k]
#define SH_P     (SH_Q + 640)         // 160 : P[m][j] basis->poly
#define SH_B     (SH_P + 160)         // 24
#define SH_F1W   (SH_B + 24)          // 192
#define SH_F1B   (SH_F1W + 192)       // 64
#define SH_V     (SH_F1B + 64)        // 128 : value head per channel
#define SH_HT    (SH_V + 128)         // 4096: hidden transposed (dead after GEMV)
#define SH_W2S   (SH_HT + 4096)       // 4096: w2 rows 2..65 stage (dead after Q build)
#define SH_TR    SH_HT                // 3968: 4 warps x [32][31], aliases HT/W2S
#define SH_TOTAL (SH_HT + 8192)       // 10456 floats = 41824 B (< 48KB default cap)

__device__ __forceinline__ float fast_tanh(float v) {
    float r;
    asm("tanh.approx.f32 %0, %1;" : "=f"(r) : "f"(v));
    return r;
}

extern "C" __global__ void __launch_bounds__(THREADS, 4)
ndp_kernel(const float* __restrict__ state,
           const float* __restrict__ fc1w, const float* __restrict__ fc1b,
           const float* __restrict__ w2,   const float* __restrict__ b2,
           const float* __restrict__ sw,   const float* __restrict__ sb,
           const float* __restrict__ vw,   const float* __restrict__ vb,
           const float* __restrict__ dc,   const float* __restrict__ ds2,
           float* __restrict__ out)
{
    extern __shared__ float sm[];
    const int tid  = threadIdx.x;
    const int bk   = blockIdx.x;
    const int lane = tid & 31;
    const int warp = tid >> 5;

    // ---- phase 1: stage weights; P in warp 0 ----
    for (int i = tid; i < 128; i += THREADS) sm[SH_WD + i] = w2[i];                // rows 0,1
    for (int i = tid; i < 64;  i += THREADS) sm[SH_WD + 128 + i] = w2[65*HID + i]; // row 65
    for (int i = tid; i < 4096; i += THREADS) sm[SH_W2S + i] = w2[2*HID + i];      // rows 2..65
    for (int i = tid; i < 128; i += THREADS) { sm[SH_SW + i] = sw[i]; sm[SH_VW + i] = vw[i]; }
    for (int i = tid; i < 192; i += THREADS) sm[SH_F1W + i] = fc1w[i];
    for (int i = tid; i < 64;  i += THREADS) sm[SH_F1B + i] = fc1b[i];
    if (tid == 0) {
        sm[SH_B + 0] = b2[0]; sm[SH_B + 1] = b2[1]; sm[SH_B + 2] = b2[65];
        sm[SH_B + 3] = sb[0]; sm[SH_B + 4] = sb[1];
        sm[SH_B + 5] = vb[0]; sm[SH_B + 6] = vb[1];
    }
    // P[m][j]: 2nd-order Taylor of exp RBF -> quartic basis (truncation ~2e-10)
    if (warp == 0) {
        float c  = dc[lane], s2 = ds2[lane];
        float a  = 0.5f / s2, a2 = a*a, c2 = c*c;
        float p0 = 1.0f - a*c2 + 0.5f*a2*c2*c2;
        float p1 = 2.0f*a*c - 2.0f*a2*c2*c;
        float p2 = -a + 3.0f*a2*c2;
        float p3 = -2.0f*a2*c;
        float p4 = 0.5f*a2;
        sm[SH_P + 0*32 + lane] = p0;
        sm[SH_P + 1*32 + lane] = p1;
        sm[SH_P + 2*32 + lane] = p2;
        sm[SH_P + 3*32 + lane] = p3;
        sm[SH_P + 4*32 + lane] = p4;
        #pragma unroll
        for (int o = 16; o; o >>= 1) {
            p0 += __shfl_xor_sync(0xffffffffu, p0, o);
            p1 += __shfl_xor_sync(0xffffffffu, p1, o);
            p2 += __shfl_xor_sync(0xffffffffu, p2, o);
            p3 += __shfl_xor_sync(0xffffffffu, p3, o);
            p4 += __shfl_xor_sync(0xffffffffu, p4, o);
        }
        if (lane == 0) {
            sm[SH_B + 7]  = p0; sm[SH_B + 8]  = p1; sm[SH_B + 9] = p2;
            sm[SH_B + 10] = p3; sm[SH_B + 11] = p4;
        }
    }
    __syncthreads();

    // ---- phase 2: fc1 hidden (transposed [64][64]), XR table, Q, C ----
    {
        int bb = tid & 63;
        int gb = bk*BPB + bb;
        float s0 = state[gb*3+0], s1 = state[gb*3+1], s2v = state[gb*3+2];
        for (int hh = (tid >> 6); hh < HID; hh += 2) {
            float v = sm[SH_F1W + hh*3+0]*s0 + sm[SH_F1W + hh*3+1]*s1
                    + sm[SH_F1W + hh*3+2]*s2v + sm[SH_F1B + hh];
            sm[SH_HT + hh*64 + bb] = fast_tanh(v) * 0.1f;
        }
    }
    {
        float S0 = sm[SH_B+7], S1 = sm[SH_B+8], S2 = sm[SH_B+9],
              S3 = sm[SH_B+10], S4 = sm[SH_B+11];
        float l2 = log2f(1.0f - DTC);
        for (int k = tid; k < TSTEPS; k += THREADS) {
            float x = exp2f((float)(k + 1) * l2);
            float S = __fmaf_rn(__fmaf_rn(__fmaf_rn(__fmaf_rn(S4,x,S3),x,S2),x,S1),x,S0);
            sm[SH_XR + 2*k]     = x;
            sm[SH_XR + 2*k + 1] = __fdividef(x * DTC, S);
        }
    }
    // Q[d][m][k] = sum_j w2s[(d*32+j)*64 + k] * P[m][j]   (all LDS)
    for (int o = tid; o < 2*5*HID; o += THREADS) {
        int k = o & 63;
        int m = (o >> 6) % 5;
        int d = o / (5*HID);
        const float* wr = sm + SH_W2S + (d*32)*HID + k;
        float acc = 0.0f;
        #pragma unroll 8
        for (int j = 0; j < NBASIS; j++)
            acc += wr[j*HID] * sm[SH_P + m*32 + j];
        sm[SH_Q + o] = acc;
    }
    if (tid < 10) {
        int d = tid / 5, m = tid % 5;
        float acc = 0.0f;
        for (int j = 0; j < NBASIS; j++)
            acc += b2[2 + d*32 + j] * sm[SH_P + m*32 + j];
        sm[SH_B + 12 + tid] = acc;
    }
    __syncthreads();

    // ---- per-channel GEMV ----
    const int b  = tid >> 1;
    const int d  = tid & 1;
    const int gb = bk*BPB + b;

    float goal = sm[SH_B + d];
    float azv  = sm[SH_B + 2];
    float sgp  = sm[SH_B + 3 + d];
    float vlp  = sm[SH_B + 5 + d];
    float c0 = sm[SH_B + 12 + d*5 + 0], c1 = sm[SH_B + 12 + d*5 + 1];
    float c2 = sm[SH_B + 12 + d*5 + 2], c3 = sm[SH_B + 12 + d*5 + 3];
    float c4 = sm[SH_B + 12 + d*5 + 4];

    #pragma unroll
    for (int k = 0; k < HID; k += 4) {
        float h0 = sm[SH_HT + (k+0)*64 + b];
        float h1 = sm[SH_HT + (k+1)*64 + b];
        float h2 = sm[SH_HT + (k+2)*64 + b];
        float h3 = sm[SH_HT + (k+3)*64 + b];
        float4 wg = *(const float4*)(sm + SH_WD + d*64 + k);
        goal += h0*wg.x + h1*wg.y + h2*wg.z + h3*wg.w;
        float4 wa = *(const float4*)(sm + SH_WD + 128 + k);
        azv  += h0*wa.x + h1*wa.y + h2*wa.z + h3*wa.w;
        float4 ws = *(const float4*)(sm + SH_SW + d*64 + k);
        sgp  += h0*ws.x + h1*ws.y + h2*ws.z + h3*ws.w;
        float4 wvv = *(const float4*)(sm + SH_VW + d*64 + k);
        vlp  += h0*wvv.x + h1*wvv.y + h2*wvv.z + h3*wvv.w;
        float4 q;
        q = *(const float4*)(sm + SH_Q + (d*5+0)*64 + k);
        c0 += h0*q.x + h1*q.y + h2*q.z + h3*q.w;
        q = *(const float4*)(sm + SH_Q + (d*5+1)*64 + k);
        c1 += h0*q.x + h1*q.y + h2*q.z + h3*q.w;
        q = *(const float4*)(sm + SH_Q + (d*5+2)*64 + k);
        c2 += h0*q.x + h1*q.y + h2*q.z + h3*q.w;
        q = *(const float4*)(sm + SH_Q + (d*5+3)*64 + k);
        c3 += h0*q.x + h1*q.y + h2*q.z + h3*q.w;
        q = *(const float4*)(sm + SH_Q + (d*5+4)*64 + k);
        c4 += h0*q.x + h1*q.y + h2*q.z + h3*q.w;
    }
    __syncthreads();   // HT reads done -> TR may alias

    azv = fminf(fmaxf(azv, 0.5f), 30.0f);
    out[OFF_SIG + (size_t)bk*THREADS + tid] = 1.0f / (1.0f + expf(-sgp)) + 0.001f;
    sm[SH_V + tid] = vlp;

    const float y0 = state[gb*3 + d];
    const float G  = goal - y0;
    c0 *= G; c1 *= G; c2 *= G; c3 *= G; c4 *= G;

    const float bz  = azv * 0.25f;
    const float P1  = DTC * azv * bz;
    const float Pg  = P1 * goal;
    const float nP1 = -P1;
    const float K1  = 1.0f - DTC * azv;

    // ---- DMP rollout: phase-A (parallel poly) / phase-B (serial chain) ----
    float y = y0, z = 0.01f;
    float* trb   = sm + SH_TR + warp*(32*31);
    float* out_a = out + (size_t)bk*THREADS*TSTEPS;
    const float2* xr = (const float2*)(sm + SH_XR);

    for (int ch = 0; ch < 10; ch++) {
        // A: 30 independent poly evals; LDS + Horner pipeline freely
        float pre[30];
        #pragma unroll
        for (int s = 0; s < 30; s++) {
            float2 xv = xr[ch*30 + s];
            float h = __fmaf_rn(__fmaf_rn(__fmaf_rn(__fmaf_rn(c4, xv.x, c3),
                                                    xv.x, c2), xv.x, c1), xv.x, c0);
            pre[s] = __fmaf_rn(h, xv.y, Pg);
        }
        // B: irreducible serial recurrence (exact output quantization)
        #pragma unroll
        for (int s = 0; s < 30; s++) {
            float u    = __fmaf_rn(nP1, y, pre[s]);    // uses OLD y
            float inc  = __fmul_rn(z, DTC);
            float ynew = __fadd_rn(y, inc);
            trb[lane*31 + s] = ynew - y;               // Sterbenz-exact a[t]
            z = __fmaf_rn(K1, z, u);                   // uses OLD z
            y = ynew;
        }
        __syncwarp();
        int t0 = ch*30;
        #pragma unroll
        for (int i = 0; i < 32; i++) {
            if (lane < 30)
                out_a[(size_t)(warp*32 + i)*TSTEPS + t0 + lane] = trb[i*31 + lane];
        }
        __syncwarp();
    }

    // ---- value broadcast fill: 4 warps x 32 channels, coalesced float4 ----
    float* out_v = out + OFF_VAL + (size_t)bk*THREADS*TSTEPS;
    #pragma unroll 4
    for (int c = 0; c < 32; c++) {
        int chn = warp*32 + c;
        float v = sm[SH_V + chn];
        float4 vv = make_float4(v, v, v, v);
        float* base = out_v + (size_t)chn*TSTEPS;
        *(float4*)(base + 4*lane)        = vv;
        *(float4*)(base + 4*(32 + lane)) = vv;
        if (lane < 11) *(float4*)(base + 4*(64 + lane)) = vv;   // 75 = 32+32+11
    }
}

extern "C" void kernel_launch(void* const* d_in, const int* in_sizes, int n_in,
                              void* d_out, int out_size)
{
    (void)in_sizes; (void)n_in; (void)out_size;
    cudaFuncSetAttribute(ndp_kernel, cudaFuncAttributeMaxDynamicSharedMemorySize,
                         SH_TOTAL * (int)sizeof(float));
    ndp_kernel<<<NBLOCKS, THREADS, SH_TOTAL * sizeof(float)>>>(
        (const float*)d_in[0],  (const float*)d_in[1], (const float*)d_in[2],
        (const float*)d_in[3],  (const float*)d_in[4], (const float*)d_in[5],
        (const float*)d_in[6],  (const float*)d_in[7], (const float*)d_in[8],
        (const float*)d_in[9],  (const float*)d_in[10], (float*)d_out);
}

// round 10
// speedup vs baseline: 1.1770x; 1.0061x over previous
#include <cuda_runtime.h>
#include <math.h>

#define BATCH   16384
#define TSTEPS  300
#define NBASIS  32
#define HID     64
#define DTC     (1.0f/300.0f)
#define BPB     64               // batches per block
#define THREADS 256              // warps 0-3: rollout (128 ch), warps 4-7: storers
#define NBLOCKS (BATCH/BPB)      // 256

#define OFF_SIG ((size_t)BATCH*2*TSTEPS)
#define OFF_VAL (OFF_SIG + (size_t)BATCH*2)

// ---- shared memory layout (floats) ----
#define SH_XR4   0                    // 600 : (x0,x1,r0,r1) per step-pair, 150 entries
#define SH_ST    600                  // 192 : state [64][3]
#define SH_WD    792                  // 192 : w2 rows 0,1,65
#define SH_SW    984                  // 128
#define SH_VW    1112                 // 128
#define SH_Q     1240                 // 640 : poly-coeff map [d][m][k]
#define SH_P     1880                 // 160 : P[m][j]
#define SH_B     2040                 // 24
#define SH_F1W   2064                 // 192
#define SH_F1B   2256                 // 64
#define SH_V     2320                 // 128 : value head per channel
#define SH_HT    2448                 // 4096: hidden [32 kpair][64 b][2] (dead after GEMV)
#define SH_W2S   6544                 // 4096: w2 rows 2..65 stage (dead after Q)
#define SH_TRB   SH_HT                // 2 x 3968: double-buffered transpose, aliases HT/W2S
#define SH_TOTAL 10640                // 42560 B < 48KB default cap

typedef unsigned long long ull;

__device__ __forceinline__ ull pack2(float lo, float hi) {
    ull r; asm("mov.b64 %0,{%1,%2};" : "=l"(r) : "f"(lo), "f"(hi)); return r;
}
__device__ __forceinline__ void unpack2(ull v, float& lo, float& hi) {
    asm("mov.b64 {%0,%1},%2;" : "=f"(lo), "=f"(hi) : "l"(v));
}
__device__ __forceinline__ ull fma2(ull a, ull b, ull c) {
    ull r; asm("fma.rn.f32x2 %0,%1,%2,%3;" : "=l"(r) : "l"(a), "l"(b), "l"(c)); return r;
}
__device__ __forceinline__ float fast_tanh(float v) {
    float r; asm("tanh.approx.f32 %0, %1;" : "=f"(r) : "f"(v)); return r;
}
__device__ __forceinline__ float hadd2(ull v) {
    float lo, hi; unpack2(v, lo, hi); return lo + hi;
}

extern "C" __global__ void __launch_bounds__(THREADS)
ndp_kernel(const float* __restrict__ state,
           const float* __restrict__ fc1w, const float* __restrict__ fc1b,
           const float* __restrict__ w2,   const float* __restrict__ b2,
           const float* __restrict__ sw,   const float* __restrict__ sb,
           const float* __restrict__ vw,   const float* __restrict__ vb,
           const float* __restrict__ dc,   const float* __restrict__ ds2,
           float* __restrict__ out)
{
    extern __shared__ float sm[];
    const int tid  = threadIdx.x;
    const int bk   = blockIdx.x;
    const int lane = tid & 31;
    const int warp = tid >> 5;

    // ---- setup: stage everything (all 256 threads) ----
    for (int i = tid; i < 192;  i += THREADS) sm[SH_ST + i]  = state[bk*BPB*3 + i];
    for (int i = tid; i < 128;  i += THREADS) sm[SH_WD + i]  = w2[i];
    for (int i = tid; i < 64;   i += THREADS) sm[SH_WD + 128 + i] = w2[65*HID + i];
    for (int i = tid; i < 4096; i += THREADS) sm[SH_W2S + i] = w2[2*HID + i];
    for (int i = tid; i < 128;  i += THREADS) { sm[SH_SW + i] = sw[i]; sm[SH_VW + i] = vw[i]; }
    for (int i = tid; i < 192;  i += THREADS) sm[SH_F1W + i] = fc1w[i];
    for (int i = tid; i < 64;   i += THREADS) sm[SH_F1B + i] = fc1b[i];
    if (tid == 0) {
        sm[SH_B + 0] = b2[0]; sm[SH_B + 1] = b2[1]; sm[SH_B + 2] = b2[65];
        sm[SH_B + 3] = sb[0]; sm[SH_B + 4] = sb[1];
        sm[SH_B + 5] = vb[0]; sm[SH_B + 6] = vb[1];
    }
    // P[m][j]: quartic basis from 2nd-order Taylor of RBF (trunc ~2e-10); warp 0
    if (warp == 0) {
        float c  = dc[lane], s2 = ds2[lane];
        float a  = 0.5f / s2, a2 = a*a, c2 = c*c;
        float p0 = 1.0f - a*c2 + 0.5f*a2*c2*c2;
        float p1 = 2.0f*a*c - 2.0f*a2*c2*c;
        float p2 = -a + 3.0f*a2*c2;
        float p3 = -2.0f*a2*c;
        float p4 = 0.5f*a2;
        sm[SH_P + 0*32 + lane] = p0;  sm[SH_P + 1*32 + lane] = p1;
        sm[SH_P + 2*32 + lane] = p2;  sm[SH_P + 3*32 + lane] = p3;
        sm[SH_P + 4*32 + lane] = p4;
        #pragma unroll
        for (int o = 16; o; o >>= 1) {
            p0 += __shfl_xor_sync(0xffffffffu, p0, o);
            p1 += __shfl_xor_sync(0xffffffffu, p1, o);
            p2 += __shfl_xor_sync(0xffffffffu, p2, o);
            p3 += __shfl_xor_sync(0xffffffffu, p3, o);
            p4 += __shfl_xor_sync(0xffffffffu, p4, o);
        }
        if (lane == 0) {
            sm[SH_B + 7]  = p0; sm[SH_B + 8]  = p1; sm[SH_B + 9] = p2;
            sm[SH_B + 10] = p3; sm[SH_B + 11] = p4;
        }
    }
    __syncthreads();

    // ---- fc1 hidden: [32 kpair][64 b][2] float2 layout for FMA2 GEMV ----
    for (int idx = tid; idx < BPB*HID; idx += THREADS) {
        int k = idx >> 6, b = idx & 63;
        float s0 = sm[SH_ST + b*3+0], s1 = sm[SH_ST + b*3+1], s2v = sm[SH_ST + b*3+2];
        float v = sm[SH_F1W + k*3+0]*s0 + sm[SH_F1W + k*3+1]*s1
                + sm[SH_F1W + k*3+2]*s2v + sm[SH_F1B + k];
        sm[SH_HT + (k >> 1)*128 + b*2 + (k & 1)] = fast_tanh(v) * 0.1f;
    }
    // ---- XR4 table: entry p covers steps 2p,2p+1; x=(1-DT)^(s+1), rdt=DT*x/S(x) ----
    {
        float S0 = sm[SH_B+7], S1 = sm[SH_B+8], S2 = sm[SH_B+9],
              S3 = sm[SH_B+10], S4 = sm[SH_B+11];
        float l2 = log2f(1.0f - DTC);
        for (int p = tid; p < TSTEPS/2; p += THREADS) {
            float x0 = exp2f((float)(2*p + 1) * l2);
            float x1 = exp2f((float)(2*p + 2) * l2);
            float Sa = __fmaf_rn(__fmaf_rn(__fmaf_rn(__fmaf_rn(S4,x0,S3),x0,S2),x0,S1),x0,S0);
            float Sb = __fmaf_rn(__fmaf_rn(__fmaf_rn(__fmaf_rn(S4,x1,S3),x1,S2),x1,S1),x1,S0);
            float4 e = make_float4(x0, x1, __fdividef(x0*DTC, Sa), __fdividef(x1*DTC, Sb));
            *(float4*)(sm + SH_XR4 + p*4) = e;
        }
    }
    // ---- Q[d][m][k] = sum_j w2s[(d*32+j)*64+k] * P[m][j] ----
    for (int o = tid; o < 2*5*HID; o += THREADS) {
        int k = o & 63, m = (o >> 6) % 5, d = o / (5*HID);
        const float* wr = sm + SH_W2S + (d*32)*HID + k;
        float acc = 0.0f;
        #pragma unroll 8
        for (int j = 0; j < NBASIS; j++)
            acc += wr[j*HID] * sm[SH_P + m*32 + j];
        sm[SH_Q + o] = acc;
    }
    if (tid < 10) {
        int d = tid / 5, m = tid % 5;
        float acc = 0.0f;
        for (int j = 0; j < NBASIS; j++)
            acc += b2[2 + d*32 + j] * sm[SH_P + m*32 + j];
        sm[SH_B + 12 + tid] = acc;
    }
    __syncthreads();

    if (warp < 4) {
        // ================= COMPUTE WARPS: channel = tid (0..127) =================
        const int b = tid >> 1, d = tid & 1;

        // GEMV: 7 accumulators in f32x2 pairs
        ull a_goal = pack2(sm[SH_B + d], 0.f);
        ull a_az   = pack2(sm[SH_B + 2], 0.f);
        ull a_c0   = pack2(sm[SH_B + 12 + d*5 + 0], 0.f);
        ull a_c1   = pack2(sm[SH_B + 12 + d*5 + 1], 0.f);
        ull a_c2   = pack2(sm[SH_B + 12 + d*5 + 2], 0.f);
        ull a_c3   = pack2(sm[SH_B + 12 + d*5 + 3], 0.f);
        ull a_c4   = pack2(sm[SH_B + 12 + d*5 + 4], 0.f);
        #pragma unroll
        for (int k = 0; k < HID; k += 4) {
            ull hA = *(const ull*)(sm + SH_HT + (k>>1)*128 + b*2);
            ull hB = *(const ull*)(sm + SH_HT + ((k>>1)+1)*128 + b*2);
            ulonglong2 q;
            q = *(const ulonglong2*)(sm + SH_WD + d*64 + k);
            a_goal = fma2(hA, q.x, fma2(hB, q.y, a_goal));
            q = *(const ulonglong2*)(sm + SH_WD + 128 + k);
            a_az   = fma2(hA, q.x, fma2(hB, q.y, a_az));
            q = *(const ulonglong2*)(sm + SH_Q + (d*5+0)*64 + k);
            a_c0   = fma2(hA, q.x, fma2(hB, q.y, a_c0));
            q = *(const ulonglong2*)(sm + SH_Q + (d*5+1)*64 + k);
            a_c1   = fma2(hA, q.x, fma2(hB, q.y, a_c1));
            q = *(const ulonglong2*)(sm + SH_Q + (d*5+2)*64 + k);
            a_c2   = fma2(hA, q.x, fma2(hB, q.y, a_c2));
            q = *(const ulonglong2*)(sm + SH_Q + (d*5+3)*64 + k);
            a_c3   = fma2(hA, q.x, fma2(hB, q.y, a_c3));
            q = *(const ulonglong2*)(sm + SH_Q + (d*5+4)*64 + k);
            a_c4   = fma2(hA, q.x, fma2(hB, q.y, a_c4));
        }
        float goal = hadd2(a_goal);
        float azv  = fminf(fmaxf(hadd2(a_az), 0.5f), 30.0f);
        float c0 = hadd2(a_c0), c1 = hadd2(a_c1), c2 = hadd2(a_c2),
              c3 = hadd2(a_c3), c4 = hadd2(a_c4);

        const float y0 = sm[SH_ST + b*3 + d];
        const float G  = goal - y0;
        c0 *= G; c1 *= G; c2 *= G; c3 *= G; c4 *= G;
        const float bz  = azv * 0.25f;
        const float P1  = DTC * azv * bz;
        const float Pg  = P1 * goal;
        const float nP1 = -P1;
        const float K1  = 1.0f - DTC * azv;

        const ull c0p = pack2(c0, c0), c1p = pack2(c1, c1), c2p = pack2(c2, c2),
                  c3p = pack2(c3, c3), c4p = pack2(c4, c4), pgp = pack2(Pg, Pg);

        float y = y0, z = 0.01f;
        float* out_a = out + (size_t)bk*128*TSTEPS;

        __syncthreads();                 // HT dead -> trb alias safe (sync #0)
        for (int i = 0; i <= 10; i++) {
            if (i < 10) {
                float* trb = sm + SH_TRB + (i & 1)*3968 + warp*992;
                // A: 15 pairs, f32x2 (bit-identical halves to scalar FFMA)
                ull pre2[15];
                #pragma unroll
                for (int sp = 0; sp < 15; sp++) {
                    ulonglong2 t = *(const ulonglong2*)(sm + SH_XR4 + (i*15 + sp)*4);
                    ull h = fma2(fma2(fma2(fma2(c4p, t.x, c3p), t.x, c2p),
                                      t.x, c1p), t.x, c0p);
                    pre2[sp] = fma2(h, t.y, pgp);
                }
                // B: serial chain, exact output quantization
                #pragma unroll
                for (int sp = 0; sp < 15; sp++) {
                    float p0, p1; unpack2(pre2[sp], p0, p1);
                    float u, inc, ynew;
                    u    = __fmaf_rn(nP1, y, p0);
                    inc  = __fmul_rn(z, DTC);
                    ynew = __fadd_rn(y, inc);
                    trb[lane*31 + 2*sp] = ynew - y;      // Sterbenz-exact
                    z = __fmaf_rn(K1, z, u);  y = ynew;
                    u    = __fmaf_rn(nP1, y, p1);
                    inc  = __fmul_rn(z, DTC);
                    ynew = __fadd_rn(y, inc);
                    trb[lane*31 + 2*sp + 1] = ynew - y;
                    z = __fmaf_rn(K1, z, u);  y = ynew;
                }
            }
            __syncthreads();
        }
        (void)out_a;
    } else {
        // ================= STORER WARPS: st = tid-128 (0..127) =================
        const int st = tid - 128;
        const int b = st >> 1, d = st & 1;
        // sigma / value head GEMV (2 dots)
        ull a_sg = pack2(sm[SH_B + 3 + d], 0.f);
        ull a_vl = pack2(sm[SH_B + 5 + d], 0.f);
        #pragma unroll
        for (int k = 0; k < HID; k += 4) {
            ull hA = *(const ull*)(sm + SH_HT + (k>>1)*128 + b*2);
            ull hB = *(const ull*)(sm + SH_HT + ((k>>1)+1)*128 + b*2);
            ulonglong2 q;
            q = *(const ulonglong2*)(sm + SH_SW + d*64 + k);
            a_sg = fma2(hA, q.x, fma2(hB, q.y, a_sg));
            q = *(const ulonglong2*)(sm + SH_VW + d*64 + k);
            a_vl = fma2(hA, q.x, fma2(hB, q.y, a_vl));
        }
        float sgp = hadd2(a_sg), vlp = hadd2(a_vl);
        out[OFF_SIG + (size_t)bk*128 + st] = 1.0f / (1.0f + expf(-sgp)) + 0.001f;
        sm[SH_V + st] = vlp;

        float* out_a = out + (size_t)bk*128*TSTEPS;
        float* out_v = out + OFF_VAL + (size_t)bk*128*TSTEPS;
        const int w = warp - 4;                    // paired compute warp / channel block

        __syncthreads();                 // matches compute sync #0 (SH_V also published)
        for (int i = 0; i <= 10; i++) {
            if (i == 0) {
                // value broadcast fill: warp w covers channels w*32..w*32+31
                #pragma unroll 4
                for (int c = 0; c < 32; c++) {
                    int chn = w*32 + c;
                    float v = sm[SH_V + chn];
                    float4 vv = make_float4(v, v, v, v);
                    float* base = out_v + (size_t)chn*TSTEPS;
                    *(float4*)(base + 4*lane)        = vv;
                    *(float4*)(base + 4*(32 + lane)) = vv;
                    if (lane < 11) *(float4*)(base + 4*(64 + lane)) = vv;
                }
            } else {
                // drain chunk i-1 from buffer (i-1)&1 (disjoint from compute's i&1)
                const float* trb = sm + SH_TRB + ((i-1) & 1)*3968 + w*992;
                int t0 = (i-1)*30;
                #pragma unroll
                for (int r = 0; r < 32; r++) {
                    if (lane < 30)
                        out_a[(size_t)(w*32 + r)*TSTEPS + t0 + lane] = trb[r*31 + lane];
                }
            }
            __syncthreads();
        }
    }
}

extern "C" void kernel_launch(void* const* d_in, const int* in_sizes, int n_in,
                              void* d_out, int out_size)
{
    (void)in_sizes; (void)n_in; (void)out_size;
    cudaFuncSetAttribute(ndp_kernel, cudaFuncAttributeMaxDynamicSharedMemorySize,
                         SH_TOTAL * (int)sizeof(float));
    ndp_kernel<<<NBLOCKS, THREADS, SH_TOTAL * sizeof(float)>>>(
        (const float*)d_in[0],  (const float*)d_in[1], (const float*)d_in[2],
        (const float*)d_in[3],  (const float*)d_in[4], (const float*)d_in[5],
        (const float*)d_in[6],  (const float*)d_in[7], (const float*)d_in[8],
        (const float*)d_in[9],  (const float*)d_in[10], (float*)d_out);
}